// round 7
// baseline (speedup 1.0000x reference)
#include <cuda_runtime.h>
#include <math.h>

#define VOC      50257
#define VOC_BULK 50256            // divisible by 4
#define EMB      128
#define N_MEM    8192
#define T_Q      50
#define T_M      50
#define N_HOPS   3

#define NB   148                  // one block per SM, all co-resident
#define TBK  1024
#define WPB  32
#define NW   (NB * WPB)           // 4736 warps

#define SHIFT 24.0f               // constant softmax shift (cancels exactly)

// ---------------- scratch ----------------
__device__ float g_u[EMB];
__device__ float g_pv[VOC + 8];
__device__ float g_sTA[N_MEM];
__device__ float g_cw[VOC];
__device__ float g_wo[N_HOPS][EMB];
__device__ float g_den[N_HOPS];
__device__ float g_plmax[NB];
__device__ float g_plden[NB];
__device__ unsigned g_arrive;
__device__ volatile unsigned g_gen;

__device__ __forceinline__ float dot4(float4 a, float4 b) {
    return fmaf(a.x, b.x, fmaf(a.y, b.y, fmaf(a.z, b.z, a.w * b.w)));
}
__device__ __forceinline__ float warp_sum(float p) {
#pragma unroll
    for (int o = 16; o; o >>= 1) p += __shfl_xor_sync(0xFFFFFFFFu, p, o);
    return p;
}
__device__ __forceinline__ void quad_reduce(float& p0, float& p1, float& p2, float& p3) {
#pragma unroll
    for (int o = 16; o; o >>= 1) {
        p0 += __shfl_xor_sync(0xFFFFFFFFu, p0, o);
        p1 += __shfl_xor_sync(0xFFFFFFFFu, p1, o);
        p2 += __shfl_xor_sync(0xFFFFFFFFu, p2, o);
        p3 += __shfl_xor_sync(0xFFFFFFFFu, p3, o);
    }
}

// generation-based grid barrier; all NB blocks co-resident (1 per SM)
__device__ __forceinline__ void grid_sync(unsigned target) {
    __syncthreads();
    if (threadIdx.x == 0) {
        __threadfence();
        unsigned a = atomicAdd(&g_arrive, 1u);
        if (a == NB - 1) {
            atomicExch(&g_arrive, 0u);
            __threadfence();
            atomicExch((unsigned*)&g_gen, target);
        } else {
            while (g_gen != target) __nanosleep(64);
        }
        __threadfence();
    }
    __syncthreads();
}

__global__ void __launch_bounds__(TBK, 1) k_fused(
    const int* __restrict__ query, const int* __restrict__ story,
    const float* __restrict__ Wa,  const float* __restrict__ Wc,
    const float* __restrict__ Wb,
    const float* __restrict__ Wt_w, const float* __restrict__ Wt_b,
    const float* __restrict__ H_w,  const float* __restrict__ H_b,
    const float* __restrict__ wout,
    const float* __restrict__ TA,  const float* __restrict__ TC,
    float* __restrict__ out)
{
    __shared__ __align__(16) float su[EMB];
    __shared__ __align__(16) float sswo[EMB];
    __shared__ float sacc[WPB][EMB];      // 16 KB reduce buffer
    __shared__ float sm[WPB], sd[WPB];
    __shared__ float sdd[2 * EMB];
    __shared__ unsigned s_base;
    __shared__ float s_c;

    int tid = threadIdx.x, lane = tid & 31, wid = tid >> 5;
    int blk = blockIdx.x;
    int gw  = blk * WPB + wid;
    unsigned nsync = 0;

    if (tid == 0) s_base = g_gen;
    __syncthreads();

    // ---------- phase A: zero scratch, compute u0 ----------
    for (int i = blk * TBK + tid; i < VOC; i += NB * TBK) g_cw[i] = 0.f;
    if (blk == 1 && tid < N_HOPS * EMB) ((float*)g_wo)[tid] = 0.f;
    if (blk == 2 && tid < N_HOPS) g_den[tid] = 0.f;
    if (blk == 0 && tid < EMB) {
        float a = 0.f;
#pragma unroll 10
        for (int t = 0; t < T_Q; t++) a += Wb[(long)__ldg(query + t) * EMB + tid];
        g_u[tid] = a;
    }
    grid_sync(s_base + ++nsync);

    if (tid < EMB) su[tid] = g_u[tid];
    __syncthreads();

    // ---------- hops ----------
    for (int hop = 0; hop < N_HOPS; hop++) {
        float4 uu = ((const float4*)su)[lane];

        // pv = Wa.u (and tail), sTA = TA.u
        for (int r0 = gw * 4; r0 < VOC_BULK; r0 += NW * 4) {
            const float4* a = (const float4*)(Wa + (long)r0 * EMB);
            float4 v0 = a[lane], v1 = a[32 + lane], v2 = a[64 + lane], v3 = a[96 + lane];
            float p0 = dot4(v0, uu), p1 = dot4(v1, uu), p2 = dot4(v2, uu), p3 = dot4(v3, uu);
            quad_reduce(p0, p1, p2, p3);
            if (lane == 0) *((float4*)(g_pv + r0)) = make_float4(p0, p1, p2, p3);
        }
        if (gw == 0) {
            float p = warp_sum(dot4(((const float4*)(Wa + (long)VOC_BULK * EMB))[lane], uu));
            if (lane == 0) g_pv[VOC_BULK] = p;
        }
        for (int r0 = gw * 4; r0 < N_MEM; r0 += NW * 4) {
            const float4* a = (const float4*)(TA + (long)r0 * EMB);
            float4 v0 = a[lane], v1 = a[32 + lane], v2 = a[64 + lane], v3 = a[96 + lane];
            float p0 = dot4(v0, uu), p1 = dot4(v1, uu), p2 = dot4(v2, uu), p3 = dot4(v3, uu);
            quad_reduce(p0, p1, p2, p3);
            if (lane == 0) *((float4*)(g_sTA + r0)) = make_float4(p0, p1, p2, p3);
        }
        grid_sync(s_base + ++nsync);

        // memory phase: warp per memory (2 per warp); score gather, scatter cw, w*TC
        {
            float dloc = 0.f;
            float4 acc = make_float4(0.f, 0.f, 0.f, 0.f);
            for (int n = gw; n < N_MEM; n += NW) {
                const int* srow = story + (long)n * T_M;
                int tok0 = srow[lane];
                float sp = __ldg(g_pv + tok0);
                int tok1 = -1;
                if (lane < T_M - 32) { tok1 = srow[lane + 32]; sp += __ldg(g_pv + tok1); }
                float s = warp_sum(sp);
                float w = __expf(s + g_sTA[n] - SHIFT);   // identical on all lanes
                if (lane == 0) dloc += w;
                atomicAdd(&g_cw[tok0], w);
                if (tok1 >= 0) atomicAdd(&g_cw[tok1], w);
                float4 v = ((const float4*)(TC + (long)n * EMB))[lane];
                acc.x += w * v.x; acc.y += w * v.y; acc.z += w * v.z; acc.w += w * v.w;
            }
            if (lane == 0) atomicAdd(&g_den[hop], dloc);
            sacc[wid][lane * 4 + 0] = acc.x;
            sacc[wid][lane * 4 + 1] = acc.y;
            sacc[wid][lane * 4 + 2] = acc.z;
            sacc[wid][lane * 4 + 3] = acc.w;
            __syncthreads();
            if (tid < EMB) {
                float v = 0.f;
#pragma unroll
                for (int w2 = 0; w2 < WPB; w2++) v += sacc[w2][tid];
                atomicAdd(&g_wo[hop][tid], v);
            }
        }
        grid_sync(s_base + ++nsync);

        // wo += Wc^T.cw ; owner warp zeroes its cw rows for the next hop
        {
            float4 acc = make_float4(0.f, 0.f, 0.f, 0.f);
            for (int r0 = gw * 4; r0 < VOC_BULK; r0 += NW * 4) {
                const float4* a = (const float4*)(Wc + (long)r0 * EMB);
                float c0 = g_cw[r0 + 0], c1 = g_cw[r0 + 1];
                float c2 = g_cw[r0 + 2], c3 = g_cw[r0 + 3];
                float4 v0 = a[lane], v1 = a[32 + lane], v2 = a[64 + lane], v3 = a[96 + lane];
                if (lane == 0) *((float4*)(g_cw + r0)) = make_float4(0.f, 0.f, 0.f, 0.f);
                acc.x += c0 * v0.x + c1 * v1.x + c2 * v2.x + c3 * v3.x;
                acc.y += c0 * v0.y + c1 * v1.y + c2 * v2.y + c3 * v3.y;
                acc.z += c0 * v0.z + c1 * v1.z + c2 * v2.z + c3 * v3.z;
                acc.w += c0 * v0.w + c1 * v1.w + c2 * v2.w + c3 * v3.w;
            }
            if (gw == 0) {
                float c = g_cw[VOC_BULK];
                float4 v = ((const float4*)(Wc + (long)VOC_BULK * EMB))[lane];
                if (lane == 0) g_cw[VOC_BULK] = 0.f;
                acc.x += c * v.x; acc.y += c * v.y; acc.z += c * v.z; acc.w += c * v.w;
            }
            sacc[wid][lane * 4 + 0] = acc.x;
            sacc[wid][lane * 4 + 1] = acc.y;
            sacc[wid][lane * 4 + 2] = acc.z;
            sacc[wid][lane * 4 + 3] = acc.w;
            __syncthreads();
            if (tid < EMB) {
                float v = 0.f;
#pragma unroll
                for (int w2 = 0; w2 < WPB; w2++) v += sacc[w2][tid];
                atomicAdd(&g_wo[hop][tid], v);
            }
        }
        grid_sync(s_base + ++nsync);

        // gated update (redundant per block; avoids another barrier)
        if (tid < EMB) sswo[tid] = g_wo[hop][tid] / g_den[hop];
        __syncthreads();
        {
            int rr0 = wid * 8;                    // 32 warps x 8 rows = 256 dots
#pragma unroll 2
            for (int j = 0; j < 8; j++) {
                int rr = rr0 + j;
                const float* W   = (rr < EMB) ? (Wt_w + (long)rr * EMB)
                                              : (H_w + (long)(rr - EMB) * EMB);
                const float* vec = (rr < EMB) ? su : sswo;
                float p = warp_sum(dot4(((const float4*)W)[lane], ((const float4*)vec)[lane]));
                if (lane == 0) sdd[rr] = p;
            }
        }
        __syncthreads();
        float unew = 0.f;
        if (tid < EMB) {
            float t = 1.f / (1.f + __expf(-(sdd[tid] + Wt_b[tid])));
            unew = su[tid] * (1.f - t) + (sdd[EMB + tid] + H_b[tid]) * t;
        }
        __syncthreads();
        if (tid < EMB) su[tid] = unew;
        __syncthreads();
    }

    // ---------- logits + online max/expsum ----------
    {
        float4 uu = ((const float4*)su)[lane];
        float m = -INFINITY, d = 0.f;
        if (gw == 0) {
            float p = warp_sum(dot4(((const float4*)(wout + (long)VOC_BULK * EMB))[lane], uu));
            if (lane == 0) out[VOC_BULK] = p;
            m = p; d = 1.f;
        }
        for (int r0 = gw * 4; r0 < VOC_BULK; r0 += NW * 4) {
            const float4* a = (const float4*)(wout + (long)r0 * EMB);
            float4 v0 = a[lane], v1 = a[32 + lane], v2 = a[64 + lane], v3 = a[96 + lane];
            float p0 = dot4(v0, uu), p1 = dot4(v1, uu), p2 = dot4(v2, uu), p3 = dot4(v3, uu);
            quad_reduce(p0, p1, p2, p3);
            if (lane == 0) *((float4*)(out + r0)) = make_float4(p0, p1, p2, p3);
            float mn = fmaxf(m, fmaxf(fmaxf(p0, p1), fmaxf(p2, p3)));
            d = d * __expf(m - mn) + __expf(p0 - mn) + __expf(p1 - mn)
                                   + __expf(p2 - mn) + __expf(p3 - mn);
            m = mn;
        }
        if (lane == 0) { sm[wid] = m; sd[wid] = d; }
        __syncthreads();
        if (tid < 32) {
            float mm = sm[tid], dd = sd[tid];
#pragma unroll
            for (int o = 16; o; o >>= 1) {
                float mo  = __shfl_xor_sync(0xFFFFFFFFu, mm, o);
                float ddo = __shfl_xor_sync(0xFFFFFFFFu, dd, o);
                float mn  = fmaxf(mm, mo);
                dd = dd * __expf(mm - mn) + ddo * __expf(mo - mn);
                mm = mn;
            }
            if (tid == 0) { g_plmax[blk] = mm; g_plden[blk] = dd; }
        }
    }
    grid_sync(s_base + ++nsync);

    // redundant combine of 148 partials, then normalize own slice
    if (tid < 32) {
        float mm = -INFINITY, dd = 0.f;
        for (int b = lane; b < NB; b += 32) {
            float mo = g_plmax[b], ddo = g_plden[b];
            float mn = fmaxf(mm, mo);
            dd = dd * __expf(mm - mn) + ddo * __expf(mo - mn);
            mm = mn;
        }
#pragma unroll
        for (int o = 16; o; o >>= 1) {
            float mo  = __shfl_xor_sync(0xFFFFFFFFu, mm, o);
            float ddo = __shfl_xor_sync(0xFFFFFFFFu, dd, o);
            float mn  = fmaxf(mm, mo);
            dd = dd * __expf(mm - mn) + ddo * __expf(mo - mn);
            mm = mn;
        }
        if (lane == 0) s_c = mm + logf(dd);
    }
    __syncthreads();
    {
        float c = s_c;
        int idx = blk * TBK + tid;                 // 151552 threads >= VOC
        if (idx < VOC) out[idx] -= c;
    }
}

// ---------------- launch ----------------
extern "C" void kernel_launch(void* const* d_in, const int* in_sizes, int n_in,
                              void* d_out, int out_size) {
    const int*   query = (const int*)  d_in[0];
    const int*   story = (const int*)  d_in[1];
    const float* Wa    = (const float*)d_in[2];
    const float* Wc    = (const float*)d_in[3];
    const float* Wb    = (const float*)d_in[4];
    const float* Wt_w  = (const float*)d_in[5];
    const float* Wt_b  = (const float*)d_in[6];
    const float* H_w   = (const float*)d_in[7];
    const float* H_b   = (const float*)d_in[8];
    const float* wout  = (const float*)d_in[9];
    const float* TA    = (const float*)d_in[10];
    const float* TC    = (const float*)d_in[11];
    float* out = (float*)d_out;

    k_fused<<<NB, TBK>>>(query, story, Wa, Wc, Wb, Wt_w, Wt_b, H_w, H_b,
                         wout, TA, TC, out);
}

// round 8
// speedup vs baseline: 1.1860x; 1.1860x over previous
#include <cuda_runtime.h>
#include <math.h>

#define VOC      50257
#define VOC_BULK 50256           // divisible by 8
#define OCT_V    (VOC_BULK / 8)  // 6282 vocab row-octets
#define EMB      128
#define N_MEM    8192
#define OCT_M    (N_MEM / 8)     // 1024 memory row-octets
#define T_Q      50
#define T_M      50
#define N_HOPS   3

#define NBV  592                 // stream blocks (4/SM, one wave)
#define TBV  256
#define WPB  8
#define NWV  (NBV * WPB)         // 4736 warps

#define NBM  128                 // memory-space kernel
#define TBM  64

#define SHIFT 24.0f              // constant softmax shift (cancels exactly)
#define NEGBIG (-1e30f)

// ---------------- scratch ----------------
__device__ __align__(16) float g_u[EMB];
__device__ __align__(16) float g_pv[VOC + 8];
__device__ __align__(16) float g_sTA[N_MEM];
__device__ __align__(16) float g_cw[VOC + 8];
__device__ __align__(16) float g_wo[EMB];
__device__ float g_den;
__device__ float g_plmax[NBV];
__device__ float g_plden[NBV];

__device__ __forceinline__ float dot4(float4 a, float4 b) {
    return fmaf(a.x, b.x, fmaf(a.y, b.y, fmaf(a.z, b.z, a.w * b.w)));
}
__device__ __forceinline__ float warp_sum(float p) {
#pragma unroll
    for (int o = 16; o; o >>= 1) p += __shfl_xor_sync(0xFFFFFFFFu, p, o);
    return p;
}
__device__ __forceinline__ void oct_reduce(float* p) {
#pragma unroll
    for (int o = 16; o; o >>= 1) {
#pragma unroll
        for (int j = 0; j < 8; j++)
            p[j] += __shfl_xor_sync(0xFFFFFFFFu, p[j], o);
    }
}

// ---------------- u0 = sum_t Wb[query[t]] ----------------
__global__ void k_u0(const int* __restrict__ q, const float* __restrict__ Wb) {
    int e = threadIdx.x;
    float a = 0.f;
#pragma unroll 10
    for (int t = 0; t < T_Q; t++) a += Wb[(long)__ldg(q + t) * EMB + e];
    g_u[e] = a;
}

// ---------------- pv = Wa.u ; sTA = TA.u ; zero cw/wo/den ----------------
__global__ void __launch_bounds__(TBV) k_pv(const float* __restrict__ Wa,
                                            const float* __restrict__ TA) {
    __shared__ float4 su4[32];
    int tid = threadIdx.x, lane = tid & 31, wid = tid >> 5;
    int gid = blockIdx.x * TBV + tid;
    if (gid < VOC) g_cw[gid] = 0.f;
    if (blockIdx.x == 0) {
        if (tid < EMB) g_wo[tid] = 0.f;
        if (tid == EMB) g_den = 0.f;
    }
    if (tid < 32) su4[tid] = ((const float4*)g_u)[tid];
    __syncthreads();
    float4 uu = su4[lane];
    int gw = blockIdx.x * WPB + wid;

    // vocab octets: two-stage (8 independent loads, then math)
    for (int oc = gw; oc < OCT_V; oc += NWV) {
        const float4* a = (const float4*)(Wa + (long)oc * 8 * EMB);
        float4 v[8];
#pragma unroll
        for (int j = 0; j < 8; j++) v[j] = a[j * 32 + lane];
        float p[8];
#pragma unroll
        for (int j = 0; j < 8; j++) p[j] = dot4(v[j], uu);
        oct_reduce(p);
        if (lane == 0) {
            float4* dst = (float4*)(g_pv + oc * 8);
            dst[0] = make_float4(p[0], p[1], p[2], p[3]);
            dst[1] = make_float4(p[4], p[5], p[6], p[7]);
        }
    }
    // memory octets
    for (int oc = gw; oc < OCT_M; oc += NWV) {
        const float4* a = (const float4*)(TA + (long)oc * 8 * EMB);
        float4 v[8];
#pragma unroll
        for (int j = 0; j < 8; j++) v[j] = a[j * 32 + lane];
        float p[8];
#pragma unroll
        for (int j = 0; j < 8; j++) p[j] = dot4(v[j], uu);
        oct_reduce(p);
        if (lane == 0) {
            float4* dst = (float4*)(g_sTA + oc * 8);
            dst[0] = make_float4(p[0], p[1], p[2], p[3]);
            dst[1] = make_float4(p[4], p[5], p[6], p[7]);
        }
    }
    if (gw == 0) {   // tail row
        float p = warp_sum(dot4(((const float4*)(Wa + (long)VOC_BULK * EMB))[lane], uu));
        if (lane == 0) g_pv[VOC_BULK] = p;
    }
}

// ---------------- per-memory: score gather, w=exp, denom, scatter cw, w*TC ----------------
__global__ void k_hopmem(const int* __restrict__ story, const float* __restrict__ TC) {
    __shared__ int   sst[TBM * T_M];
    __shared__ float sw[TBM];
    __shared__ float sred[TBM / 32];
    __shared__ float sacc[TBM / 32][EMB];
    int tid = threadIdx.x, lane = tid & 31, wid = tid >> 5;

    long base = (long)blockIdx.x * TBM * T_M;
#pragma unroll 4
    for (int i = tid; i < TBM * T_M; i += TBM) sst[i] = story[base + i];
    __syncthreads();

    int n = blockIdx.x * TBM + tid;
    float s = g_sTA[n];
#pragma unroll 10
    for (int t = 0; t < T_M; t++) s += g_pv[sst[tid * T_M + t]];
    float w = __expf(s - SHIFT);
    sw[tid] = w;

    float d = warp_sum(w);
    if (lane == 0) sred[wid] = d;

#pragma unroll 10
    for (int t = 0; t < T_M; t++) atomicAdd(&g_cw[sst[tid * T_M + t]], w);
    __syncthreads();

    if (tid == 0) {
        float db = 0.f;
#pragma unroll
        for (int i = 0; i < TBM / 32; i++) db += sred[i];
        atomicAdd(&g_den, db);
    }

    float4 acc = make_float4(0.f, 0.f, 0.f, 0.f);
    for (int j = wid; j < TBM; j += TBM / 32) {
        float wn = sw[j];
        float4 v = ((const float4*)(TC + (long)(blockIdx.x * TBM + j) * EMB))[lane];
        acc.x += wn * v.x; acc.y += wn * v.y; acc.z += wn * v.z; acc.w += wn * v.w;
    }
    sacc[wid][lane * 4 + 0] = acc.x;
    sacc[wid][lane * 4 + 1] = acc.y;
    sacc[wid][lane * 4 + 2] = acc.z;
    sacc[wid][lane * 4 + 3] = acc.w;
    __syncthreads();
    if (tid < EMB / 2) {
#pragma unroll
        for (int k = 0; k < 2; k++) {
            int e = tid * 2 + k;
            float v = 0.f;
#pragma unroll
            for (int w2 = 0; w2 < TBM / 32; w2++) v += sacc[w2][e];
            atomicAdd(&g_wo[e], v);
        }
    }
}

// ---------------- wo += Wc^T.cw ----------------
__global__ void __launch_bounds__(TBV) k_wo(const float* __restrict__ Wc) {
    __shared__ float sacc[WPB][EMB];
    int tid = threadIdx.x, lane = tid & 31, wid = tid >> 5;
    int gw = blockIdx.x * WPB + wid;

    float4 acc = make_float4(0.f, 0.f, 0.f, 0.f);
    for (int oc = gw; oc < OCT_V; oc += NWV) {
        const float4* a = (const float4*)(Wc + (long)oc * 8 * EMB);
        float4 c4a = ((const float4*)g_cw)[oc * 2 + 0];   // broadcast
        float4 c4b = ((const float4*)g_cw)[oc * 2 + 1];
        float4 v[8];
#pragma unroll
        for (int j = 0; j < 8; j++) v[j] = a[j * 32 + lane];
        float c[8] = {c4a.x, c4a.y, c4a.z, c4a.w, c4b.x, c4b.y, c4b.z, c4b.w};
#pragma unroll
        for (int j = 0; j < 8; j++) {
            acc.x = fmaf(c[j], v[j].x, acc.x);
            acc.y = fmaf(c[j], v[j].y, acc.y);
            acc.z = fmaf(c[j], v[j].z, acc.z);
            acc.w = fmaf(c[j], v[j].w, acc.w);
        }
    }
    if (gw == 0) {   // tail row
        float c = g_cw[VOC_BULK];
        float4 v = ((const float4*)(Wc + (long)VOC_BULK * EMB))[lane];
        acc.x = fmaf(c, v.x, acc.x); acc.y = fmaf(c, v.y, acc.y);
        acc.z = fmaf(c, v.z, acc.z); acc.w = fmaf(c, v.w, acc.w);
    }
    sacc[wid][lane * 4 + 0] = acc.x;
    sacc[wid][lane * 4 + 1] = acc.y;
    sacc[wid][lane * 4 + 2] = acc.z;
    sacc[wid][lane * 4 + 3] = acc.w;
    __syncthreads();
    if (tid < EMB) {
        float v = 0.f;
#pragma unroll
        for (int w2 = 0; w2 < WPB; w2++) v += sacc[w2][tid];
        atomicAdd(&g_wo[tid], v);
    }
}

// ---------------- gated update of u ----------------
__global__ void k_update(const float* __restrict__ Wt_w, const float* __restrict__ Wt_b,
                         const float* __restrict__ H_w,  const float* __restrict__ H_b) {
    __shared__ __align__(16) float su[EMB], swo[EMB], sdt[EMB], sdh[EMB];
    int tid = threadIdx.x, lane = tid & 31, wid = tid >> 5;
    if (tid < EMB) {
        su[tid]  = g_u[tid];
        swo[tid] = g_wo[tid] / g_den;
    }
    __syncthreads();

    const float* W   = (wid < 4) ? Wt_w : H_w;
    const float* vec = (wid < 4) ? su : swo;
    float*       dst = (wid < 4) ? sdt : sdh;
    float4 v4 = ((const float4*)vec)[lane];
    int r0 = (wid & 3) * 32;
#pragma unroll 4
    for (int j = 0; j < 32; j++) {
        int row = r0 + j;
        float4 w4 = ((const float4*)(W + (long)row * EMB))[lane];
        float p = warp_sum(dot4(w4, v4));
        if (lane == 0) dst[row] = p;
    }
    __syncthreads();
    if (tid < EMB) {
        float t = 1.f / (1.f + __expf(-(sdt[tid] + Wt_b[tid])));
        g_u[tid] = su[tid] * (1.f - t) + (sdh[tid] + H_b[tid]) * t;
    }
}

// ---------------- logits + online partials ----------------
__global__ void __launch_bounds__(TBV) k_logits(const float* __restrict__ wout,
                                                float* __restrict__ out) {
    __shared__ float4 su4[32];
    __shared__ float sm[WPB], sd[WPB];
    int tid = threadIdx.x, lane = tid & 31, wid = tid >> 5;
    if (tid < 32) su4[tid] = ((const float4*)g_u)[tid];
    __syncthreads();
    float4 uu = su4[lane];
    int gw = blockIdx.x * WPB + wid;

    float m = NEGBIG, d = 0.f;
    if (gw == 0) {   // tail row
        float p = warp_sum(dot4(((const float4*)(wout + (long)VOC_BULK * EMB))[lane], uu));
        if (lane == 0) out[VOC_BULK] = p;
        m = p; d = 1.f;
    }
    for (int oc = gw; oc < OCT_V; oc += NWV) {
        const float4* a = (const float4*)(wout + (long)oc * 8 * EMB);
        float4 v[8];
#pragma unroll
        for (int j = 0; j < 8; j++) v[j] = a[j * 32 + lane];
        float p[8];
#pragma unroll
        for (int j = 0; j < 8; j++) p[j] = dot4(v[j], uu);
        oct_reduce(p);
        if (lane == 0) {
            float4* dst = (float4*)(out + oc * 8);
            dst[0] = make_float4(p[0], p[1], p[2], p[3]);
            dst[1] = make_float4(p[4], p[5], p[6], p[7]);
        }
        float mx = p[0];
#pragma unroll
        for (int j = 1; j < 8; j++) mx = fmaxf(mx, p[j]);
        float mn = fmaxf(m, mx);
        float dn = d * __expf(m - mn);
#pragma unroll
        for (int j = 0; j < 8; j++) dn += __expf(p[j] - mn);
        m = mn; d = dn;
    }
    if (lane == 0) { sm[wid] = m; sd[wid] = d; }
    __syncthreads();
    if (tid < 32) {
        float mm = (tid < WPB) ? sm[tid] : NEGBIG;
        float dd = (tid < WPB) ? sd[tid] : 0.f;
#pragma unroll
        for (int o = 4; o; o >>= 1) {
            float mo  = __shfl_xor_sync(0xFFFFFFFFu, mm, o);
            float ddo = __shfl_xor_sync(0xFFFFFFFFu, dd, o);
            float mn  = fmaxf(mm, mo);
            dd = dd * __expf(mm - mn) + ddo * __expf(mo - mn);
            mm = mn;
        }
        if (tid == 0) { g_plmax[blockIdx.x] = mm; g_plden[blockIdx.x] = dd; }
    }
}

// ---------------- combine partials + normalize ----------------
__global__ void k_norm(float* __restrict__ out) {
    __shared__ float sc;
    int tid = threadIdx.x, lane = tid & 31;
    if (tid < 32) {
        float mm = NEGBIG, dd = 0.f;
        for (int b = lane; b < NBV; b += 32) {
            float mo = g_plmax[b], ddo = g_plden[b];
            float mn = fmaxf(mm, mo);
            dd = dd * __expf(mm - mn) + ddo * __expf(mo - mn);
            mm = mn;
        }
#pragma unroll
        for (int o = 16; o; o >>= 1) {
            float mo  = __shfl_xor_sync(0xFFFFFFFFu, mm, o);
            float ddo = __shfl_xor_sync(0xFFFFFFFFu, dd, o);
            float mn  = fmaxf(mm, mo);
            dd = dd * __expf(mm - mn) + ddo * __expf(mo - mn);
            mm = mn;
        }
        if (tid == 0) sc = mm + logf(dd);
    }
    __syncthreads();
    float c = sc;
    float4* o4 = (float4*)out;
    for (int i = blockIdx.x * blockDim.x + tid; i < VOC_BULK / 4; i += gridDim.x * blockDim.x) {
        float4 v = o4[i];
        v.x -= c; v.y -= c; v.z -= c; v.w -= c;
        o4[i] = v;
    }
    if (blockIdx.x == 0 && tid == 0) out[VOC_BULK] -= c;
}

// ---------------- launch ----------------
extern "C" void kernel_launch(void* const* d_in, const int* in_sizes, int n_in,
                              void* d_out, int out_size) {
    const int*   query = (const int*)  d_in[0];
    const int*   story = (const int*)  d_in[1];
    const float* Wa    = (const float*)d_in[2];
    const float* Wc    = (const float*)d_in[3];
    const float* Wb    = (const float*)d_in[4];
    const float* Wt_w  = (const float*)d_in[5];
    const float* Wt_b  = (const float*)d_in[6];
    const float* H_w   = (const float*)d_in[7];
    const float* H_b   = (const float*)d_in[8];
    const float* wout  = (const float*)d_in[9];
    const float* TA    = (const float*)d_in[10];
    const float* TC    = (const float*)d_in[11];
    float* out = (float*)d_out;

    k_u0<<<1, EMB>>>(query, Wb);

    for (int h = 0; h < N_HOPS; h++) {
        k_pv    <<<NBV, TBV>>>(Wa, TA);
        k_hopmem<<<NBM, TBM>>>(story, TC);
        k_wo    <<<NBV, TBV>>>(Wc);
        k_update<<<1, 256>>>(Wt_w, Wt_b, H_w, H_b);
    }

    k_logits<<<NBV, TBV>>>(wout, out);
    k_norm  <<<148, 256>>>(out);
}